// round 16
// baseline (speedup 1.0000x reference)
#include <cuda_runtime.h>
#include <math.h>

#define E 4
#define L 10
#define MM 512
#define FF 128
#define SS 1000

typedef unsigned long long ull;

// ---------------- device scratch (static: no allocations allowed) ----------
__device__ float    g_proj[E * L * FF * MM];   // proj transposed: [e][l][f][m], 10.5 MB
__device__ float    g_s1[E * L * 4 * FF];      // per-(el,chunk,f) sum x
__device__ float    g_s2[E * L * 4 * FF];      // per-(el,chunk,f) sum x^2
__device__ float    g_invstd;
__device__ unsigned g_minbits;
__device__ unsigned g_maxbits;

// ordered-uint encoding of float for atomicMin/Max
__device__ __forceinline__ unsigned fenc(float f) {
    unsigned u = __float_as_uint(f);
    return (u & 0x80000000u) ? ~u : (u | 0x80000000u);
}
__device__ __forceinline__ float fdec(unsigned e) {
    unsigned u = (e & 0x80000000u) ? (e ^ 0x80000000u) : ~e;
    return __uint_as_float(u);
}

// ---------------- packed f32x2 helpers (Blackwell FFMA2 path) ---------------
__device__ __forceinline__ ull pk2(float lo, float hi) {
    ull r;
    asm("mov.b64 %0, {%1, %2};" : "=l"(r) : "r"(__float_as_uint(lo)), "r"(__float_as_uint(hi)));
    return r;
}
__device__ __forceinline__ void upk2(ull p, float& lo, float& hi) {
    unsigned a, b;
    asm("mov.b64 {%0, %1}, %2;" : "=r"(a), "=r"(b) : "l"(p));
    lo = __uint_as_float(a); hi = __uint_as_float(b);
}
__device__ __forceinline__ ull f2mul(ull a, ull b) {
    ull r; asm("mul.rn.f32x2 %0, %1, %2;" : "=l"(r) : "l"(a), "l"(b)); return r;
}
__device__ __forceinline__ ull f2add(ull a, ull b) {
    ull r; asm("add.rn.f32x2 %0, %1, %2;" : "=l"(r) : "l"(a), "l"(b)); return r;
}
__device__ __forceinline__ ull f2fma(ull a, ull b, ull c) {
    ull r; asm("fma.rn.f32x2 %0, %1, %2, %3;" : "=l"(r) : "l"(a), "l"(b), "l"(c)); return r;
}
__device__ __forceinline__ float ex2f(float a) {
    float r; asm("ex2.approx.ftz.f32 %0, %1;" : "=f"(r) : "f"(a)); return r;
}

// ---------------- K1: raw partial sums for std, 160 blocks ------------------
__global__ void k1_std(const float* __restrict__ matrix) {
    int bl = blockIdx.x >> 2;       // e*L + l
    int q  = blockIdx.x & 3;        // M chunk
    int f  = threadIdx.x;           // feature
    const float* base = matrix + (size_t)bl * MM * FF + (size_t)q * 128 * FF + f;
    float s = 0.f, s2 = 0.f;
#pragma unroll 16
    for (int m = 0; m < 128; m++) {
        float x = base[(size_t)m * FF];
        s += x; s2 += x * x;
    }
    g_s1[blockIdx.x * FF + f] = s;
    g_s2[blockIdx.x * FF + f] = s2;
}

// ---------------- K2: combine partials -> invstd; init min/max --------------
__global__ __launch_bounds__(1024) void k2_red() {
    int t = threadIdx.x;
    if (t == 0) { g_minbits = 0xFFFFFFFFu; g_maxbits = 0u; }
    float acc = 0.f;
    for (int it = t; it < E * L * FF; it += 1024) {
        int bl = it >> 7;       // 0..39
        int f  = it & 127;
        float s = 0.f, s2 = 0.f;
#pragma unroll
        for (int q = 0; q < 4; q++) {
            s  += g_s1[(bl * 4 + q) * FF + f];
            s2 += g_s2[(bl * 4 + q) * FF + f];
        }
        float mean = s * (1.f / MM);
        float var  = fmaxf(s2 * (1.f / MM) - mean * mean, 0.f);
        acc += sqrtf(var);
    }
    __shared__ float red[1024];
    red[t] = acc; __syncthreads();
    for (int o = 512; o > 0; o >>= 1) { if (t < o) red[t] += red[t + o]; __syncthreads(); }
    if (t == 0) g_invstd = (float)(E * L * FF) / red[0];
}

// ---------------- K3: proj = (matrix @ params) * invstd, fused min/max ------
// 640 blocks, 256 threads, 64x64 tile, packed f32x2 FMAs (best measured cfg).
__global__ __launch_bounds__(256) void k3_gemm(const float* __restrict__ A,
                                               const float* __restrict__ B) {
    __shared__ float As[32 * 68];    // As[k][m], pad 68 -> float4-aligned LDS
    __shared__ float Bs[32 * 68];    // Bs[k][g]
    int tid = threadIdx.x;
    int tx = tid & 15, ty = tid >> 4;
    int bm = blockIdx.x >> 1;
    int bg = blockIdx.x & 1;
    int row0  = bm * 64;                   // global row = (e*L+l)*M + m
    int g0    = bg * 64;
    int el    = row0 / MM;
    int mbase = row0 % MM;

    ull acc2[4][2];
#pragma unroll
    for (int i = 0; i < 4; i++) { acc2[i][0] = 0ull; acc2[i][1] = 0ull; }

    const float* Ab = A + (size_t)row0 * FF;
#pragma unroll
    for (int kc = 0; kc < FF; kc += 32) {
#pragma unroll
        for (int t = 0; t < 8; t++) {
            int idx = tid + t * 256;               // 0..2047
            int kk = idx & 31, mm = idx >> 5;      // coalesced global read
            As[kk * 68 + mm] = Ab[(size_t)mm * FF + kc + kk];
        }
#pragma unroll
        for (int t = 0; t < 8; t++) {
            int idx = tid + t * 256;               // 0..2047
            int g = idx & 63, kk = idx >> 6;
            Bs[kk * 68 + g] = B[(size_t)(kc + kk) * FF + g0 + g];
        }
        __syncthreads();
#pragma unroll
        for (int kk = 0; kk < 32; kk++) {
            float4 av = *(const float4*)&As[kk * 68 + ty * 4];
            float4 bv = *(const float4*)&Bs[kk * 68 + tx * 4];
            ull b01 = pk2(bv.x, bv.y), b23 = pk2(bv.z, bv.w);
            float a[4] = {av.x, av.y, av.z, av.w};
#pragma unroll
            for (int i = 0; i < 4; i++) {
                ull ai = pk2(a[i], a[i]);
                acc2[i][0] = f2fma(ai, b01, acc2[i][0]);
                acc2[i][1] = f2fma(ai, b23, acc2[i][1]);
            }
        }
        __syncthreads();
    }

    float acc[4][4];
#pragma unroll
    for (int i = 0; i < 4; i++) {
        upk2(acc2[i][0], acc[i][0], acc[i][1]);
        upk2(acc2[i][1], acc[i][2], acc[i][3]);
    }

    float inv = g_invstd;
    float mn = INFINITY, mx = -INFINITY;
#pragma unroll
    for (int j = 0; j < 4; j++) {
        int g = g0 + tx * 4 + j;
        float v0 = acc[0][j] * inv, v1 = acc[1][j] * inv;
        float v2 = acc[2][j] * inv, v3 = acc[3][j] * inv;
        float4 o = {v0, v1, v2, v3};
        *(float4*)&g_proj[((size_t)el * FF + g) * MM + mbase + ty * 4] = o;
        mn = fminf(mn, fminf(fminf(v0, v1), fminf(v2, v3)));
        mx = fmaxf(mx, fmaxf(fmaxf(v0, v1), fmaxf(v2, v3)));
    }
    __shared__ float rmn[256], rmx[256];
    rmn[tid] = mn; rmx[tid] = mx; __syncthreads();
    for (int o = 128; o > 0; o >>= 1) {
        if (tid < o) {
            rmn[tid] = fminf(rmn[tid], rmn[tid + o]);
            rmx[tid] = fmaxf(rmx[tid], rmx[tid + o]);
        }
        __syncthreads();
    }
    if (tid == 0) {
        atomicMin(&g_minbits, fenc(rmn[0]));
        atomicMax(&g_maxbits, fenc(rmx[0]));
    }
}

// ---------------- K4: KDE grid sums + pairwise L1, parity-balanced ----------
// block = (l,f); 8 warps. For env e, warp w handles x-chunk (w + 2e + b) & 7.
// Chain: 1 EX2 (K0) per sample; ratio rho0 = 2^(ru*u0+rc) via degree-3 packed
// polynomial (|arg| <= ~0.22 where contributions matter; rel err ~2e-5).
__global__ __launch_bounds__(256) void k4_main(const int* __restrict__ data_len,
                                               const void* __restrict__ itrain,
                                               float* __restrict__ out) {
    int b = blockIdx.x;
    int l = b / FF, f = b % FF;
    int tid = threadIdx.x;
    int lane = tid & 31;
    int warp = tid >> 5;

    __shared__ float sv[E][MM];
    __shared__ __align__(16) float lst[8][516];   // per-warp compacted values
    __shared__ __align__(16) float sr[E][1024];   // per-point sums exchange
    __shared__ int   slen[E];
    __shared__ float sinvlen[E];
    __shared__ float wred[8][6];
    for (int e = 0; e < E; e++) {
        const float* src = g_proj + ((size_t)(e * L + l) * FF + f) * MM;
        for (int idx = tid; idx < MM; idx += 256) sv[e][idx] = src[idx];
    }
    if (tid < E) {
        int le = data_len[tid * L + l];
        slen[tid] = le;
        sinvlen[tid] = 1.0f / (float)le;
    }
    __syncthreads();

    float left  = fdec(g_minbits);
    float right = fdec(g_maxbits);
    float h     = (right - left) * (1.0f / (SS - 1));   // linspace spacing
    float delta = (right - left) * (1.0f / SS);         // reference's delta

    // bw = 1.06 * 512^(-1/5) exactly (mean std of normalized matrix == 1)
    const double bwd = 1.06 * exp2(-1.8);
    const double cd  = 0.5 / (bwd * bwd);
    const float CL   = (float)(cd * 1.4426950408889634); // c * log2(e)
    const float divisor = (float)(2.5066282746310002 * bwd);

    const float ru  = 2.0f * h * CL;
    const float rc  = -h * h * CL;
    const float sig = exp2f(-2.0f * h * h * CL);
    const float sig3 = sig * sig * sig;
    const ull NCL2 = pk2(-CL, -CL);
    const ull RU2  = pk2(ru, ru);
    const ull RC2  = pk2(rc, rc);
    const ull SIGA = pk2(sig, sig);
    const ull SIGB = pk2(sig3, sig3);
    // degree-3 Taylor of 2^x (|x| small): 1 + x(ln2 + x(ln2^2/2 + x ln2^3/6))
    const ull PC3 = pk2(0.05550411f, 0.05550411f);
    const ull PC2 = pk2(0.24022651f, 0.24022651f);
    const ull PC1 = pk2(0.69314718f, 0.69314718f);
    const ull ONE2 = pk2(1.0f, 1.0f);

    const float W = 0.85f;                // tail exp(-c*0.7225) ~ 2e-2, cancels in diffs
    float thresh = W + 64.f * h;
    unsigned lmlt = (1u << lane) - 1u;

#pragma unroll
    for (int e = 0; e < E; e++) {
        int ch = (warp + 2 * e + b) & 7;       // parity-balanced chunk assignment
        float xmid = left + ((float)(ch * 128) + 63.5f) * h;
        float x0   = left + (float)(ch * 128 + lane * 4) * h;
        ull NX0 = pk2(-x0, -x0);
        int n = slen[e];                       // padded rows are exactly 0 -> skip
        // --- per-warp ballot compaction: fixed 16 unrolled iterations ---
        __syncwarp();
        int c = 0;
#pragma unroll
        for (int it = 0; it < 16; it++) {
            int m = it * 32 + lane;
            float v = sv[e][m];                // array always fully populated
            bool in = (m < n) && (fabsf(v - xmid) < thresh);
            unsigned msk = __ballot_sync(0xFFFFFFFFu, in);
            if (in) lst[warp][c + __popc(msk & lmlt)] = v;
            c += __popc(msk);
        }
        int cp = (c + 3) & ~3;                 // pad to multiple of 4
        if (lane < cp - c) lst[warp][c + lane] = xmid + 40.f;  // K underflows to 0
        __syncwarp();

        // --- packed 2-sample chain evaluation (1 EX2/sample + poly rho) ---
        ull A0 = 0ull, A1 = 0ull, A2 = 0ull, A3 = 0ull;
        const float4* lp = (const float4*)&lst[warp][0];
        int n4 = cp >> 2;
        for (int i = 0; i < n4; i++) {
            float4 q = lp[i];
#pragma unroll
            for (int half = 0; half < 2; half++) {
                ull V = half ? pk2(q.z, q.w) : pk2(q.x, q.y);
                ull U  = f2add(V, NX0);          // u0 pair
                ull Sq = f2mul(U, U);
                ull Aa = f2mul(Sq, NCL2);        // -CL*u0^2
                ull AR = f2fma(U, RU2, RC2);     // x = ru*u0 + rc (small)
                float alo, ahi;
                upk2(Aa, alo, ahi);
                ull K0 = pk2(ex2f(alo), ex2f(ahi));
                // rho0 = 2^x via packed degree-3 poly (K0 underflow kills sentinels)
                ull R0 = f2fma(AR, PC3, PC2);
                R0 = f2fma(R0, AR, PC1);
                R0 = f2fma(R0, AR, ONE2);
                ull K1 = f2mul(K0, R0);
                A0 = f2add(A0, K0);
                A1 = f2add(A1, K1);
                ull R2 = f2mul(R0, R0);
                ull Ra = f2mul(R2, SIGA);        // rho0^2 sig
                ull Rb = f2mul(R2, SIGB);        // rho0^2 sig^3
                A2 = f2fma(K0, Ra, A2);
                A3 = f2fma(K1, Rb, A3);
            }
        }
        float r0, r1, r2, r3, lo, hi;
        upk2(A0, lo, hi); r0 = lo + hi;
        upk2(A1, lo, hi); r1 = lo + hi;
        upk2(A2, lo, hi); r2 = lo + hi;
        upk2(A3, lo, hi); r3 = lo + hi;
        float4 rv = {r0, r1, r2, r3};
        *(float4*)&sr[e][ch * 128 + lane * 4] = rv;   // each slot written once
        __syncwarp();
    }
    __syncthreads();

    // ---- pairwise |r_i - r_j| over this thread's 4 points (from sr) ----
    int p0 = tid * 4;
    float ps[6];
#pragma unroll
    for (int k = 0; k < 6; k++) ps[k] = 0.f;
#pragma unroll
    for (int j = 0; j < 4; j++) {
        int p = p0 + j;
        if (p < SS) {
            float r[E];
#pragma unroll
            for (int e = 0; e < E; e++) r[e] = sr[e][p] * sinvlen[e];
            int k = 0;
#pragma unroll
            for (int i = 0; i < E; i++)
#pragma unroll
                for (int jj = i + 1; jj < E; jj++) {
                    ps[k] += fabsf(r[i] - r[jj]);
                    k++;
                }
        }
    }
#pragma unroll
    for (int k = 0; k < 6; k++)
#pragma unroll
        for (int o = 16; o > 0; o >>= 1)
            ps[k] += __shfl_down_sync(0xFFFFFFFFu, ps[k], o);
    if (lane == 0) {
#pragma unroll
        for (int k = 0; k < 6; k++) wred[warp][k] = ps[k];
    }
    __syncthreads();
    if (tid == 0) {
        float tot[6];
#pragma unroll
        for (int k = 0; k < 6; k++) {
            tot[k] = 0.f;
            for (int w = 0; w < 8; w++) tot[k] += wred[w][k];
        }
        // decode is_train_env robustly (bool bytes vs int32 words)
        const int* wi = (const int*)itrain;
        bool asint = true;
        int vi[E];
        for (int i = 0; i < E; i++) { vi[i] = wi[i]; if (vi[i] != 0 && vi[i] != 1) asint = false; }
        const unsigned char* wb = (const unsigned char*)itrain;
        bool tr[E];
        for (int i = 0; i < E; i++) tr[i] = asint ? (vi[i] != 0) : (wb[i] != 0);

        float scale = delta * 0.5f / divisor;
        float testmax = -INFINITY, trainmax = -INFINITY;
        int k = 0;
        for (int i = 0; i < E; i++)
            for (int jj = i + 1; jj < E; jj++) {
                float hh = tot[k] * scale;
                testmax = fmaxf(testmax, hh);
                if (tr[i] && tr[jj]) trainmax = fmaxf(trainmax, hh);
                k++;
            }
        out[l * FF + f]          = trainmax;             // train_results [L,F]
        out[L * FF + l * FF + f] = testmax;              // test_results  [L,F]
    }
}

// ---------------- K5: final max-over-L, mean-over-F scalars -----------------
__global__ void k5_fin(float* __restrict__ out) {
    int f = threadIdx.x;    // 128
    float mtr = -INFINITY, mte = -INFINITY;
    for (int l = 0; l < L; l++) {
        mtr = fmaxf(mtr, out[l * FF + f]);
        mte = fmaxf(mte, out[L * FF + l * FF + f]);
    }
    __shared__ float r1[128], r2[128];
    r1[f] = mtr; r2[f] = mte; __syncthreads();
    for (int o = 64; o > 0; o >>= 1) {
        if (f < o) { r1[f] += r1[f + o]; r2[f] += r2[f + o]; }
        __syncthreads();
    }
    if (f == 0) {
        out[2 * L * FF]     = r1[0] / (float)FF;   // train_dis
        out[2 * L * FF + 1] = r2[0] / (float)FF;   // test_dis
    }
}

// ---------------- launcher ---------------------------------------------------
extern "C" void kernel_launch(void* const* d_in, const int* in_sizes, int n_in,
                              void* d_out, int out_size) {
    const float* matrix   = (const float*)d_in[0];  // [E,L,M,F]
    const float* params   = (const float*)d_in[1];  // [F,F]
    const int*   data_len = (const int*)d_in[2];    // [E,L]
    const void*  itrain   = d_in[3];                // [E] bool
    float* out = (float*)d_out;                     // 2562 floats

    k1_std<<<E * L * 4, 128>>>(matrix);
    k2_red<<<1, 1024>>>();
    k3_gemm<<<(E * L * MM / 64) * (FF / 64), 256>>>(matrix, params);
    k4_main<<<L * FF, 256>>>(data_len, itrain, out);
    k5_fin<<<1, 128>>>(out);
}

// round 17
// speedup vs baseline: 1.3037x; 1.3037x over previous
#include <cuda_runtime.h>
#include <math.h>

#define E 4
#define L 10
#define MM 512
#define FF 128
#define SS 1000

typedef unsigned long long ull;

// ---------------- device scratch (static: no allocations allowed) ----------
__device__ float    g_proj[E * L * FF * MM];   // proj transposed: [e][l][f][m], 10.5 MB
__device__ float    g_s1[E * L * 4 * FF];      // per-(el,chunk,f) sum x
__device__ float    g_s2[E * L * 4 * FF];      // per-(el,chunk,f) sum x^2
__device__ float    g_invstd;
__device__ unsigned g_minbits;
__device__ unsigned g_maxbits;

// ordered-uint encoding of float for atomicMin/Max
__device__ __forceinline__ unsigned fenc(float f) {
    unsigned u = __float_as_uint(f);
    return (u & 0x80000000u) ? ~u : (u | 0x80000000u);
}
__device__ __forceinline__ float fdec(unsigned e) {
    unsigned u = (e & 0x80000000u) ? (e ^ 0x80000000u) : ~e;
    return __uint_as_float(u);
}

// ---------------- packed f32x2 helpers (Blackwell FFMA2 path) ---------------
__device__ __forceinline__ ull pk2(float lo, float hi) {
    ull r;
    asm("mov.b64 %0, {%1, %2};" : "=l"(r) : "r"(__float_as_uint(lo)), "r"(__float_as_uint(hi)));
    return r;
}
__device__ __forceinline__ void upk2(ull p, float& lo, float& hi) {
    unsigned a, b;
    asm("mov.b64 {%0, %1}, %2;" : "=r"(a), "=r"(b) : "l"(p));
    lo = __uint_as_float(a); hi = __uint_as_float(b);
}
__device__ __forceinline__ ull f2mul(ull a, ull b) {
    ull r; asm("mul.rn.f32x2 %0, %1, %2;" : "=l"(r) : "l"(a), "l"(b)); return r;
}
__device__ __forceinline__ ull f2add(ull a, ull b) {
    ull r; asm("add.rn.f32x2 %0, %1, %2;" : "=l"(r) : "l"(a), "l"(b)); return r;
}
__device__ __forceinline__ ull f2fma(ull a, ull b, ull c) {
    ull r; asm("fma.rn.f32x2 %0, %1, %2, %3;" : "=l"(r) : "l"(a), "l"(b), "l"(c)); return r;
}
__device__ __forceinline__ float ex2f(float a) {
    float r; asm("ex2.approx.ftz.f32 %0, %1;" : "=f"(r) : "f"(a)); return r;
}

// ---------------- K1: raw partial sums for std, 160 blocks ------------------
__global__ void k1_std(const float* __restrict__ matrix) {
    int bl = blockIdx.x >> 2;       // e*L + l
    int q  = blockIdx.x & 3;        // M chunk
    int f  = threadIdx.x;           // feature
    const float* base = matrix + (size_t)bl * MM * FF + (size_t)q * 128 * FF + f;
    float s = 0.f, s2 = 0.f;
#pragma unroll 16
    for (int m = 0; m < 128; m++) {
        float x = base[(size_t)m * FF];
        s += x; s2 += x * x;
    }
    g_s1[blockIdx.x * FF + f] = s;
    g_s2[blockIdx.x * FF + f] = s2;
}

// ---------------- K2: combine partials -> invstd; init min/max --------------
__global__ __launch_bounds__(1024) void k2_red() {
    int t = threadIdx.x;
    if (t == 0) { g_minbits = 0xFFFFFFFFu; g_maxbits = 0u; }
    float acc = 0.f;
    for (int it = t; it < E * L * FF; it += 1024) {
        int bl = it >> 7;       // 0..39
        int f  = it & 127;
        float s = 0.f, s2 = 0.f;
#pragma unroll
        for (int q = 0; q < 4; q++) {
            s  += g_s1[(bl * 4 + q) * FF + f];
            s2 += g_s2[(bl * 4 + q) * FF + f];
        }
        float mean = s * (1.f / MM);
        float var  = fmaxf(s2 * (1.f / MM) - mean * mean, 0.f);
        acc += sqrtf(var);
    }
    __shared__ float red[1024];
    red[t] = acc; __syncthreads();
    for (int o = 512; o > 0; o >>= 1) { if (t < o) red[t] += red[t + o]; __syncthreads(); }
    if (t == 0) g_invstd = (float)(E * L * FF) / red[0];
}

// ---------------- K3: proj = (matrix @ params) * invstd, fused min/max ------
// 640 blocks, 256 threads, 64x64 tile, packed f32x2 FMAs (best measured cfg).
__global__ __launch_bounds__(256) void k3_gemm(const float* __restrict__ A,
                                               const float* __restrict__ B) {
    __shared__ float As[32 * 68];    // As[k][m], pad 68 -> float4-aligned LDS
    __shared__ float Bs[32 * 68];    // Bs[k][g]
    int tid = threadIdx.x;
    int tx = tid & 15, ty = tid >> 4;
    int bm = blockIdx.x >> 1;
    int bg = blockIdx.x & 1;
    int row0  = bm * 64;                   // global row = (e*L+l)*M + m
    int g0    = bg * 64;
    int el    = row0 / MM;
    int mbase = row0 % MM;

    ull acc2[4][2];
#pragma unroll
    for (int i = 0; i < 4; i++) { acc2[i][0] = 0ull; acc2[i][1] = 0ull; }

    const float* Ab = A + (size_t)row0 * FF;
#pragma unroll
    for (int kc = 0; kc < FF; kc += 32) {
#pragma unroll
        for (int t = 0; t < 8; t++) {
            int idx = tid + t * 256;               // 0..2047
            int kk = idx & 31, mm = idx >> 5;      // coalesced global read
            As[kk * 68 + mm] = Ab[(size_t)mm * FF + kc + kk];
        }
#pragma unroll
        for (int t = 0; t < 8; t++) {
            int idx = tid + t * 256;               // 0..2047
            int g = idx & 63, kk = idx >> 6;
            Bs[kk * 68 + g] = B[(size_t)(kc + kk) * FF + g0 + g];
        }
        __syncthreads();
#pragma unroll
        for (int kk = 0; kk < 32; kk++) {
            float4 av = *(const float4*)&As[kk * 68 + ty * 4];
            float4 bv = *(const float4*)&Bs[kk * 68 + tx * 4];
            ull b01 = pk2(bv.x, bv.y), b23 = pk2(bv.z, bv.w);
            float a[4] = {av.x, av.y, av.z, av.w};
#pragma unroll
            for (int i = 0; i < 4; i++) {
                ull ai = pk2(a[i], a[i]);
                acc2[i][0] = f2fma(ai, b01, acc2[i][0]);
                acc2[i][1] = f2fma(ai, b23, acc2[i][1]);
            }
        }
        __syncthreads();
    }

    float acc[4][4];
#pragma unroll
    for (int i = 0; i < 4; i++) {
        upk2(acc2[i][0], acc[i][0], acc[i][1]);
        upk2(acc2[i][1], acc[i][2], acc[i][3]);
    }

    float inv = g_invstd;
    float mn = INFINITY, mx = -INFINITY;
#pragma unroll
    for (int j = 0; j < 4; j++) {
        int g = g0 + tx * 4 + j;
        float v0 = acc[0][j] * inv, v1 = acc[1][j] * inv;
        float v2 = acc[2][j] * inv, v3 = acc[3][j] * inv;
        float4 o = {v0, v1, v2, v3};
        *(float4*)&g_proj[((size_t)el * FF + g) * MM + mbase + ty * 4] = o;
        mn = fminf(mn, fminf(fminf(v0, v1), fminf(v2, v3)));
        mx = fmaxf(mx, fmaxf(fmaxf(v0, v1), fmaxf(v2, v3)));
    }
    __shared__ float rmn[256], rmx[256];
    rmn[tid] = mn; rmx[tid] = mx; __syncthreads();
    for (int o = 128; o > 0; o >>= 1) {
        if (tid < o) {
            rmn[tid] = fminf(rmn[tid], rmn[tid + o]);
            rmx[tid] = fmaxf(rmx[tid], rmx[tid + o]);
        }
        __syncthreads();
    }
    if (tid == 0) {
        atomicMin(&g_minbits, fenc(rmn[0]));
        atomicMax(&g_maxbits, fenc(rmx[0]));
    }
}

// ---------------- K4: KDE grid sums + pairwise L1, parity-balanced ----------
// block = (l,f); 8 warps. For env e, warp w handles x-chunk (w + 2e + b) & 7.
// Scan: fixed 16 fully-unrolled ballot iterations (loads front-batched).
__global__ __launch_bounds__(256) void k4_main(const int* __restrict__ data_len,
                                               const void* __restrict__ itrain,
                                               float* __restrict__ out) {
    int b = blockIdx.x;
    int l = b / FF, f = b % FF;
    int tid = threadIdx.x;
    int lane = tid & 31;
    int warp = tid >> 5;

    __shared__ float sv[E][MM];
    __shared__ __align__(16) float lst[8][516];   // per-warp compacted values
    __shared__ __align__(16) float sr[E][1024];   // per-point sums exchange
    __shared__ int   slen[E];
    __shared__ float sinvlen[E];
    __shared__ float wred[8][6];
    for (int e = 0; e < E; e++) {
        const float* src = g_proj + ((size_t)(e * L + l) * FF + f) * MM;
        for (int idx = tid; idx < MM; idx += 256) sv[e][idx] = src[idx];
    }
    if (tid < E) {
        int le = data_len[tid * L + l];
        slen[tid] = le;
        sinvlen[tid] = 1.0f / (float)le;
    }
    __syncthreads();

    float left  = fdec(g_minbits);
    float right = fdec(g_maxbits);
    float h     = (right - left) * (1.0f / (SS - 1));   // linspace spacing
    float delta = (right - left) * (1.0f / SS);         // reference's delta

    // bw = 1.06 * 512^(-1/5) exactly (mean std of normalized matrix == 1)
    const double bwd = 1.06 * exp2(-1.8);
    const double cd  = 0.5 / (bwd * bwd);
    const float CL   = (float)(cd * 1.4426950408889634); // c * log2(e)
    const float divisor = (float)(2.5066282746310002 * bwd);

    const float ru  = 2.0f * h * CL;
    const float rc  = -h * h * CL;
    const float sig = exp2f(-2.0f * h * h * CL);
    const float sig3 = sig * sig * sig;
    const ull NCL2 = pk2(-CL, -CL);
    const ull RU2  = pk2(ru, ru);
    const ull RC2  = pk2(rc, rc);
    const ull SIGA = pk2(sig, sig);
    const ull SIGB = pk2(sig3, sig3);

    const float W = 0.85f;                // tail exp(-c*0.7225) ~ 2e-2, cancels in diffs
    float thresh = W + 64.f * h;
    unsigned lmlt = (1u << lane) - 1u;

#pragma unroll
    for (int e = 0; e < E; e++) {
        int ch = (warp + 2 * e + b) & 7;       // parity-balanced chunk assignment
        float xmid = left + ((float)(ch * 128) + 63.5f) * h;
        float x0   = left + (float)(ch * 128 + lane * 4) * h;
        ull NX0 = pk2(-x0, -x0);
        int n = slen[e];                       // padded rows are exactly 0 -> skip
        // --- per-warp ballot compaction: fixed 16 unrolled iterations ---
        __syncwarp();
        int c = 0;
#pragma unroll
        for (int it = 0; it < 16; it++) {
            int m = it * 32 + lane;
            float v = sv[e][m];                // array always fully populated
            bool in = (m < n) && (fabsf(v - xmid) < thresh);
            unsigned msk = __ballot_sync(0xFFFFFFFFu, in);
            if (in) lst[warp][c + __popc(msk & lmlt)] = v;
            c += __popc(msk);
        }
        int cp = (c + 3) & ~3;                 // pad to multiple of 4
        if (lane < cp - c) lst[warp][c + lane] = xmid + 40.f;  // K underflows to 0
        __syncwarp();

        // --- packed 2-sample chain evaluation ---
        ull A0 = 0ull, A1 = 0ull, A2 = 0ull, A3 = 0ull;
        const float4* lp = (const float4*)&lst[warp][0];
        int n4 = cp >> 2;
        for (int i = 0; i < n4; i++) {
            float4 q = lp[i];
#pragma unroll
            for (int half = 0; half < 2; half++) {
                ull V = half ? pk2(q.z, q.w) : pk2(q.x, q.y);
                ull U  = f2add(V, NX0);          // u0 pair
                ull Sq = f2mul(U, U);
                ull Aa = f2mul(Sq, NCL2);        // -CL*u0^2
                ull AR = f2fma(U, RU2, RC2);     // ru*u0 + rc
                float alo, ahi, rlo, rhi;
                upk2(Aa, alo, ahi); upk2(AR, rlo, rhi);
                ull K0 = pk2(ex2f(alo), ex2f(ahi));
                ull R0 = pk2(ex2f(rlo), ex2f(rhi));
                ull K1 = f2mul(K0, R0);
                A0 = f2add(A0, K0);
                A1 = f2add(A1, K1);
                ull R2 = f2mul(R0, R0);
                ull Ra = f2mul(R2, SIGA);        // rho0^2 sig
                ull Rb = f2mul(R2, SIGB);        // rho0^2 sig^3
                A2 = f2fma(K0, Ra, A2);
                A3 = f2fma(K1, Rb, A3);
            }
        }
        float r0, r1, r2, r3, lo, hi;
        upk2(A0, lo, hi); r0 = lo + hi;
        upk2(A1, lo, hi); r1 = lo + hi;
        upk2(A2, lo, hi); r2 = lo + hi;
        upk2(A3, lo, hi); r3 = lo + hi;
        float4 rv = {r0, r1, r2, r3};
        *(float4*)&sr[e][ch * 128 + lane * 4] = rv;   // each slot written once
        __syncwarp();
    }
    __syncthreads();

    // ---- pairwise |r_i - r_j| over this thread's 4 points (from sr) ----
    int p0 = tid * 4;
    float ps[6];
#pragma unroll
    for (int k = 0; k < 6; k++) ps[k] = 0.f;
#pragma unroll
    for (int j = 0; j < 4; j++) {
        int p = p0 + j;
        if (p < SS) {
            float r[E];
#pragma unroll
            for (int e = 0; e < E; e++) r[e] = sr[e][p] * sinvlen[e];
            int k = 0;
#pragma unroll
            for (int i = 0; i < E; i++)
#pragma unroll
                for (int jj = i + 1; jj < E; jj++) {
                    ps[k] += fabsf(r[i] - r[jj]);
                    k++;
                }
        }
    }
#pragma unroll
    for (int k = 0; k < 6; k++)
#pragma unroll
        for (int o = 16; o > 0; o >>= 1)
            ps[k] += __shfl_down_sync(0xFFFFFFFFu, ps[k], o);
    if (lane == 0) {
#pragma unroll
        for (int k = 0; k < 6; k++) wred[warp][k] = ps[k];
    }
    __syncthreads();
    if (tid == 0) {
        float tot[6];
#pragma unroll
        for (int k = 0; k < 6; k++) {
            tot[k] = 0.f;
            for (int w = 0; w < 8; w++) tot[k] += wred[w][k];
        }
        // decode is_train_env robustly (bool bytes vs int32 words)
        const int* wi = (const int*)itrain;
        bool asint = true;
        int vi[E];
        for (int i = 0; i < E; i++) { vi[i] = wi[i]; if (vi[i] != 0 && vi[i] != 1) asint = false; }
        const unsigned char* wb = (const unsigned char*)itrain;
        bool tr[E];
        for (int i = 0; i < E; i++) tr[i] = asint ? (vi[i] != 0) : (wb[i] != 0);

        float scale = delta * 0.5f / divisor;
        float testmax = -INFINITY, trainmax = -INFINITY;
        int k = 0;
        for (int i = 0; i < E; i++)
            for (int jj = i + 1; jj < E; jj++) {
                float hh = tot[k] * scale;
                testmax = fmaxf(testmax, hh);
                if (tr[i] && tr[jj]) trainmax = fmaxf(trainmax, hh);
                k++;
            }
        out[l * FF + f]          = trainmax;             // train_results [L,F]
        out[L * FF + l * FF + f] = testmax;              // test_results  [L,F]
    }
}

// ---------------- K5: final max-over-L, mean-over-F scalars -----------------
__global__ void k5_fin(float* __restrict__ out) {
    int f = threadIdx.x;    // 128
    float mtr = -INFINITY, mte = -INFINITY;
    for (int l = 0; l < L; l++) {
        mtr = fmaxf(mtr, out[l * FF + f]);
        mte = fmaxf(mte, out[L * FF + l * FF + f]);
    }
    __shared__ float r1[128], r2[128];
    r1[f] = mtr; r2[f] = mte; __syncthreads();
    for (int o = 64; o > 0; o >>= 1) {
        if (f < o) { r1[f] += r1[f + o]; r2[f] += r2[f + o]; }
        __syncthreads();
    }
    if (f == 0) {
        out[2 * L * FF]     = r1[0] / (float)FF;   // train_dis
        out[2 * L * FF + 1] = r2[0] / (float)FF;   // test_dis
    }
}

// ---------------- launcher ---------------------------------------------------
extern "C" void kernel_launch(void* const* d_in, const int* in_sizes, int n_in,
                              void* d_out, int out_size) {
    const float* matrix   = (const float*)d_in[0];  // [E,L,M,F]
    const float* params   = (const float*)d_in[1];  // [F,F]
    const int*   data_len = (const int*)d_in[2];    // [E,L]
    const void*  itrain   = d_in[3];                // [E] bool
    float* out = (float*)d_out;                     // 2562 floats

    k1_std<<<E * L * 4, 128>>>(matrix);
    k2_red<<<1, 1024>>>();
    k3_gemm<<<(E * L * MM / 64) * (FF / 64), 256>>>(matrix, params);
    k4_main<<<L * FF, 256>>>(data_len, itrain, out);
    k5_fin<<<1, 128>>>(out);
}